// round 2
// baseline (speedup 1.0000x reference)
#include <cuda_runtime.h>

// Problem constants (fixed by the dataset)
#define DD    256      // feature dim
#define NNODE 20000    // nodes
#define RRR   12       // relation labels (buckets = 2R)
#define EE    200000   // edges  -> 2*EE messages
#define NB    (2*RRR)  // 24 buckets

// GEMM tiling
#define TM 128
#define TN 128
#define TK 32
#define NTHREADS 256

#define MAX_TILES (2*EE/TM + NB + 8)   // 3157 upper bound on real tiles

// ---------------- device scratch (no runtime allocation allowed) -------------
__device__ int g_count[RRR];
__device__ int g_start[NB + 1];
__device__ int g_cursor[NB];
__device__ int g_src[2 * EE];
__device__ int g_dst[2 * EE];
__device__ int g_tile_info[MAX_TILES];
__device__ int g_total_tiles;

// ---------------- bucketing: counting sort of messages by relation ----------
__global__ void zero_counts_k() {
    if (threadIdx.x < RRR) g_count[threadIdx.x] = 0;
}

__global__ void hist_k(const int* __restrict__ rel) {
    __shared__ int sc[RRR];
    if (threadIdx.x < RRR) sc[threadIdx.x] = 0;
    __syncthreads();
    int i = blockIdx.x * blockDim.x + threadIdx.x;
    if (i < EE) atomicAdd(&sc[rel[i]], 1);
    __syncthreads();
    if (threadIdx.x < RRR && sc[threadIdx.x])
        atomicAdd(&g_count[threadIdx.x], sc[threadIdx.x]);
}

// single-thread scan over 24 buckets + build tile table
__global__ void scan_k() {
    if (threadIdx.x != 0) return;
    int s = 0, nt = 0;
    for (int b = 0; b < NB; b++) {
        int c = g_count[(b < RRR) ? b : (b - RRR)];  // reverse bucket has same count
        g_start[b]  = s;
        g_cursor[b] = s;
        int tiles = (c + TM - 1) / TM;
        for (int t = 0; t < tiles; t++) g_tile_info[nt++] = (b << 16) | t;
        s += c;
    }
    g_start[NB] = s;
    g_total_tiles = nt;
}

__global__ void scatter_k(const int* __restrict__ dep,
                          const int* __restrict__ rel,
                          const int* __restrict__ gov) {
    int i = blockIdx.x * blockDim.x + threadIdx.x;
    if (i >= EE) return;
    int r = rel[i], d = dep[i], g = gov[i];
    // forward: dep += W[r] @ x[gov]
    int p = atomicAdd(&g_cursor[r], 1);
    g_src[p] = g; g_dst[p] = d;
    // reverse: gov += W[r+R] @ x[dep]
    int p2 = atomicAdd(&g_cursor[r + RRR], 1);
    g_src[p2] = d; g_dst[p2] = g;
}

// ---------------- self transform: out = x @ Wself^T + bself ------------------
__global__ __launch_bounds__(NTHREADS, 2)
void self_gemm_k(const float* __restrict__ x, const float* __restrict__ Ws,
                 const float* __restrict__ bs, float* __restrict__ out) {
    __shared__ float As[TK][TM + 4];
    __shared__ float Bs[TK][TN + 4];

    const int m0 = blockIdx.x * TM;
    const int n0 = blockIdx.y * TN;
    const int tid = threadIdx.x;
    const int tx = tid & 15;   // n-sub
    const int ty = tid >> 4;   // m-sub

    float acc[8][8];
#pragma unroll
    for (int i = 0; i < 8; i++)
#pragma unroll
        for (int j = 0; j < 8; j++) acc[i][j] = 0.f;

    for (int k0 = 0; k0 < DD; k0 += TK) {
        // load A tile (rows of x)
#pragma unroll
        for (int s = 0; s < (TM * TK / 4) / NTHREADS; s++) {
            int q = tid + NTHREADS * s;
            int row = q >> 3;            // 8 float4 per row (TK=32)
            int kc  = (q & 7) * 4;
            int m = m0 + row; if (m >= NNODE) m = NNODE - 1;
            float4 v = *(const float4*)(x + (size_t)m * DD + k0 + kc);
            As[kc + 0][row] = v.x; As[kc + 1][row] = v.y;
            As[kc + 2][row] = v.z; As[kc + 3][row] = v.w;
        }
        // load B tile (rows of Wself, K-major)
#pragma unroll
        for (int s = 0; s < (TN * TK / 4) / NTHREADS; s++) {
            int q = tid + NTHREADS * s;
            int row = q >> 3;
            int kc  = (q & 7) * 4;
            float4 v = *(const float4*)(Ws + (size_t)(n0 + row) * DD + k0 + kc);
            Bs[kc + 0][row] = v.x; Bs[kc + 1][row] = v.y;
            Bs[kc + 2][row] = v.z; Bs[kc + 3][row] = v.w;
        }
        __syncthreads();
#pragma unroll
        for (int k = 0; k < TK; k++) {
            float a[8], bb[8];
#pragma unroll
            for (int i = 0; i < 8; i++) a[i]  = As[k][ty * 8 + i];
#pragma unroll
            for (int j = 0; j < 8; j++) bb[j] = Bs[k][tx * 8 + j];
#pragma unroll
            for (int i = 0; i < 8; i++)
#pragma unroll
                for (int j = 0; j < 8; j++) acc[i][j] += a[i] * bb[j];
        }
        __syncthreads();
    }

    float bias[8];
#pragma unroll
    for (int j = 0; j < 8; j++) bias[j] = bs[n0 + tx * 8 + j];

#pragma unroll
    for (int i = 0; i < 8; i++) {
        int m = m0 + ty * 8 + i;
        if (m < NNODE) {
            float* orow = out + (size_t)m * DD + n0 + tx * 8;
#pragma unroll
            for (int j = 0; j < 8; j++) orow[j] = acc[i][j] + bias[j];
        }
    }
}

// ---------------- grouped message GEMM + atomic scatter-add ------------------
__global__ __launch_bounds__(NTHREADS, 2)
void msg_gemm_k(const float* __restrict__ x, const float* __restrict__ Wr,
                const float* __restrict__ br, float* __restrict__ out) {
    const int t = blockIdx.x;
    if (t >= g_total_tiles) return;
    const int info = g_tile_info[t];
    const int b  = info >> 16;
    const int mt = info & 0xFFFF;

    const int start = g_start[b];
    const int count = g_start[b + 1] - start;
    const int m0 = mt * TM;
    const int n0 = blockIdx.y * TN;
    const float* W = Wr + (size_t)b * DD * DD;

    __shared__ float As[TK][TM + 4];
    __shared__ float Bs[TK][TN + 4];

    const int tid = threadIdx.x;
    const int tx = tid & 15;
    const int ty = tid >> 4;

    // cache gathered node indices for this thread's A-load rows
    int nodeA[(TM * TK / 4) / NTHREADS];
#pragma unroll
    for (int s = 0; s < (TM * TK / 4) / NTHREADS; s++) {
        int q = tid + NTHREADS * s;
        int row = q >> 3;
        int m = m0 + row; if (m >= count) m = count - 1;
        nodeA[s] = g_src[start + m];
    }

    float acc[8][8];
#pragma unroll
    for (int i = 0; i < 8; i++)
#pragma unroll
        for (int j = 0; j < 8; j++) acc[i][j] = 0.f;

    for (int k0 = 0; k0 < DD; k0 += TK) {
#pragma unroll
        for (int s = 0; s < (TM * TK / 4) / NTHREADS; s++) {
            int q = tid + NTHREADS * s;
            int row = q >> 3;
            int kc  = (q & 7) * 4;
            float4 v = *(const float4*)(x + (size_t)nodeA[s] * DD + k0 + kc);
            As[kc + 0][row] = v.x; As[kc + 1][row] = v.y;
            As[kc + 2][row] = v.z; As[kc + 3][row] = v.w;
        }
#pragma unroll
        for (int s = 0; s < (TN * TK / 4) / NTHREADS; s++) {
            int q = tid + NTHREADS * s;
            int row = q >> 3;
            int kc  = (q & 7) * 4;
            float4 v = *(const float4*)(W + (size_t)(n0 + row) * DD + k0 + kc);
            Bs[kc + 0][row] = v.x; Bs[kc + 1][row] = v.y;
            Bs[kc + 2][row] = v.z; Bs[kc + 3][row] = v.w;
        }
        __syncthreads();
#pragma unroll
        for (int k = 0; k < TK; k++) {
            float a[8], bb[8];
#pragma unroll
            for (int i = 0; i < 8; i++) a[i]  = As[k][ty * 8 + i];
#pragma unroll
            for (int j = 0; j < 8; j++) bb[j] = Bs[k][tx * 8 + j];
#pragma unroll
            for (int i = 0; i < 8; i++)
#pragma unroll
                for (int j = 0; j < 8; j++) acc[i][j] += a[i] * bb[j];
        }
        __syncthreads();
    }

    float bias[8];
#pragma unroll
    for (int j = 0; j < 8; j++) bias[j] = br[b * DD + n0 + tx * 8 + j];

#pragma unroll
    for (int i = 0; i < 8; i++) {
        int m = m0 + ty * 8 + i;
        if (m < count) {
            int dst = g_dst[start + m];
            float* orow = out + (size_t)dst * DD + n0 + tx * 8;
#pragma unroll
            for (int j = 0; j < 8; j++)
                atomicAdd(orow + j, acc[i][j] + bias[j]);   // no return use -> REDG
        }
    }
}

// ---------------- final ReLU -------------------------------------------------
__global__ void relu_k(float* __restrict__ out) {
    int i = blockIdx.x * blockDim.x + threadIdx.x;
    if (i < NNODE * DD / 4) {
        float4* p = (float4*)out;
        float4 v = p[i];
        v.x = fmaxf(v.x, 0.f); v.y = fmaxf(v.y, 0.f);
        v.z = fmaxf(v.z, 0.f); v.w = fmaxf(v.w, 0.f);
        p[i] = v;
    }
}

// ---------------- launch -----------------------------------------------------
extern "C" void kernel_launch(void* const* d_in, const int* in_sizes, int n_in,
                              void* d_out, int out_size) {
    (void)in_sizes; (void)n_in; (void)out_size;
    const float* x   = (const float*)d_in[0];
    const int*   dep = (const int*)d_in[1];
    const int*   rel = (const int*)d_in[2];
    const int*   gov = (const int*)d_in[3];
    const float* Ws  = (const float*)d_in[4];
    const float* bs  = (const float*)d_in[5];
    const float* Wr  = (const float*)d_in[6];
    const float* br  = (const float*)d_in[7];
    float* out = (float*)d_out;

    zero_counts_k<<<1, 32>>>();
    hist_k<<<(EE + 255) / 256, 256>>>(rel);
    scan_k<<<1, 32>>>();
    scatter_k<<<(EE + 255) / 256, 256>>>(dep, rel, gov);

    dim3 gself((NNODE + TM - 1) / TM, DD / TN);
    self_gemm_k<<<gself, NTHREADS>>>(x, Ws, bs, out);

    dim3 gmsg(MAX_TILES, DD / TN);
    msg_gemm_k<<<gmsg, NTHREADS>>>(x, Wr, br, out);

    relu_k<<<(NNODE * DD / 4 + 255) / 256, 256>>>(out);
}

// round 5
// speedup vs baseline: 3.3872x; 3.3872x over previous
#include <cuda_runtime.h>
#include <cuda_fp16.h>
#include <cstdint>

// ---------------- problem constants -----------------------------------------
#define DD    256
#define NNODE 20000
#define RRR   12
#define EE    200000
#define NB    (2*RRR)
#define TM    128
#define MAX_TILES (2*EE/TM + NB + 8)
#define NCHUNK 12            // 3 passes x 4 k64 chunks

// ---------------- smem layout -------------------------------------------------
#define SM_ROWSRC 0          // 128 int
#define SM_ROWDST 512        // 128 int
#define SM_BIAS   1024       // 128 float
#define SM_BUF    2048
#define STAGE_STRIDE 32768   // A 16KB + B 16KB
#define OFF_B     16384
#define SMEM_TOTAL (SM_BUF + 2*STAGE_STRIDE)   // 67584 B

// ---------------- device scratch ---------------------------------------------
__device__ int g_count[RRR];
__device__ int g_start[NB + 1];
__device__ int g_cursor[NB];
__device__ int g_src[2 * EE];
__device__ int g_dst[2 * EE];
__device__ int g_tile_info[MAX_TILES];
__device__ int g_total_tiles;

__device__ __half g_xh[NNODE * DD];
__device__ __half g_xl[NNODE * DD];
__device__ __half g_wh[(NB + 1) * DD * DD];   // [bucket][out=n][in=k]; index NB = W_self
__device__ __half g_wl[(NB + 1) * DD * DD];

// ---------------- PTX helpers ------------------------------------------------
__device__ __forceinline__ uint32_t smem_u32(const void* p) {
    uint32_t a;
    asm("{ .reg .u64 t; cvta.to.shared.u64 t, %1; cvt.u32.u64 %0, t; }" : "=r"(a) : "l"(p));
    return a;
}
__device__ __forceinline__ void cp16(uint32_t d, const void* s) {
    asm volatile("cp.async.cg.shared.global [%0], [%1], 16;" :: "r"(d), "l"(s) : "memory");
}
__device__ __forceinline__ void cp_commit() {
    asm volatile("cp.async.commit_group;" ::: "memory");
}
template<int N> __device__ __forceinline__ void cp_wait() {
    asm volatile("cp.async.wait_group %0;" :: "n"(N) : "memory");
}
__device__ __forceinline__ void ldsm4(uint32_t* r, uint32_t addr) {
    asm volatile("ldmatrix.sync.aligned.m8n8.x4.shared.b16 {%0,%1,%2,%3}, [%4];"
                 : "=r"(r[0]), "=r"(r[1]), "=r"(r[2]), "=r"(r[3]) : "r"(addr));
}
__device__ __forceinline__ void mma16816(float* c, const uint32_t* a, uint32_t b0, uint32_t b1) {
    asm volatile("mma.sync.aligned.m16n8k16.row.col.f32.f16.f16.f32 "
                 "{%0,%1,%2,%3}, {%4,%5,%6,%7}, {%8,%9}, {%0,%1,%2,%3};"
                 : "+f"(c[0]), "+f"(c[1]), "+f"(c[2]), "+f"(c[3])
                 : "r"(a[0]), "r"(a[1]), "r"(a[2]), "r"(a[3]), "r"(b0), "r"(b1));
}
__device__ __forceinline__ void red2(float* p, float v0, float v1) {
    asm volatile("red.global.add.v2.f32 [%0], {%1,%2};" :: "l"(p), "f"(v0), "f"(v1) : "memory");
}

// ---------------- setup kernels ----------------------------------------------
__global__ void zero_counts_k() {
    if (threadIdx.x < RRR) g_count[threadIdx.x] = 0;
}

__global__ void hist_k(const int* __restrict__ rel) {
    __shared__ int sc[RRR];
    if (threadIdx.x < RRR) sc[threadIdx.x] = 0;
    __syncthreads();
    int i = blockIdx.x * blockDim.x + threadIdx.x;
    if (i < EE) atomicAdd(&sc[rel[i]], 1);
    __syncthreads();
    if (threadIdx.x < RRR && sc[threadIdx.x])
        atomicAdd(&g_count[threadIdx.x], sc[threadIdx.x]);
}

__global__ void scan_k() {
    if (threadIdx.x != 0) return;
    int s = 0, nt = 0;
    for (int b = 0; b < NB; b++) {
        int c = g_count[(b < RRR) ? b : (b - RRR)];
        g_start[b] = s;
        g_cursor[b] = s;
        int tiles = (c + TM - 1) / TM;
        for (int t = 0; t < tiles; t++) g_tile_info[nt++] = (b << 16) | t;
        s += c;
    }
    g_start[NB] = s;
    g_total_tiles = nt;
}

// block-aggregated scatter: smem local offsets + one global atomic per (block,bucket)
__global__ void scatter2_k(const int* __restrict__ dep,
                           const int* __restrict__ rel,
                           const int* __restrict__ gov) {
    __shared__ int sc[NB];
    __shared__ int base[NB];
    int t = threadIdx.x;
    if (t < NB) sc[t] = 0;
    __syncthreads();
    int i = blockIdx.x * blockDim.x + t;
    int r = 0, d = 0, g = 0, l1 = 0, l2 = 0;
    bool v = (i < EE);
    if (v) {
        r = rel[i]; d = dep[i]; g = gov[i];
        l1 = atomicAdd(&sc[r], 1);
        l2 = atomicAdd(&sc[r + RRR], 1);
    }
    __syncthreads();
    if (t < NB) base[t] = sc[t] ? atomicAdd(&g_cursor[t], sc[t]) : 0;
    __syncthreads();
    if (v) {
        int p = base[r] + l1;         g_src[p] = g; g_dst[p] = d;   // forward
        int q = base[r + RRR] + l2;   g_src[q] = d; g_dst[q] = g;   // reverse
    }
}

// ---------------- fp16 hi/lo conversions -------------------------------------
__global__ void convert_x_k(const float* __restrict__ x) {
    int i = blockIdx.x * blockDim.x + threadIdx.x;
    if (i < NNODE * DD) {
        float v = x[i];
        __half h = __float2half_rn(v);
        g_xh[i] = h;
        g_xl[i] = __float2half_rn(v - __half2float(h));
    }
}

__global__ void convert_w_k(const float* __restrict__ Wr, const float* __restrict__ Ws) {
    int i = blockIdx.x * blockDim.x + threadIdx.x;
    if (i >= (NB + 1) * DD * DD) return;
    int b = i >> 16;
    float v = (b < NB) ? Wr[i] : Ws[i & 65535];
    __half h = __float2half_rn(v);
    g_wh[i] = h;
    g_wl[i] = __float2half_rn(v - __half2float(h));
}

// ---------------- grouped GEMM via mma.sync (HMMA) ----------------------------
// CTA: 128(M) x 128(N); grid.y in {0,1} selects N half. 8 warps, warp tile 32x64.
// K_eff = 768: pass0 xh*wh, pass1 xh*wl, pass2 xl*wh (fp16 split, fp32 accum).
template<bool SELF>
__global__ __launch_bounds__(256, 2)
void gemm_mma_k(const float* __restrict__ bvec_g, float* __restrict__ out) {
    extern __shared__ char smem[];
    const int tid = threadIdx.x, lid = tid & 31, wid = tid >> 5;
    const int wm = wid >> 1, wn = wid & 1;          // warp grid 4 x 2
    const int n0 = blockIdx.y * 128;

    int b = 0, m0, start = 0, count;
    if (SELF) {
        m0 = blockIdx.x * TM;
        count = NNODE;
    } else {
        if (blockIdx.x >= g_total_tiles) return;
        int info = g_tile_info[blockIdx.x];
        b = info >> 16;
        m0 = (info & 0xFFFF) * TM;
        start = g_start[b];
        count = g_start[b + 1] - start;
    }

    int*   row_src = (int*)smem;
    int*   row_dst = (int*)(smem + SM_ROWDST);
    float* bias    = (float*)(smem + SM_BIAS);
    uint32_t sb = smem_u32(smem);

    if (tid < 128) {
        int m = m0 + tid; if (m >= count) m = count - 1;
        int s, d;
        if (SELF) { s = m; d = m; }
        else      { s = g_src[start + m]; d = g_dst[start + m]; }
        row_src[tid] = s;
        row_dst[tid] = d;
        bias[tid] = SELF ? bvec_g[n0 + tid] : bvec_g[b * DD + n0 + tid];
    }
    __syncthreads();

    const size_t wbase = (size_t)(SELF ? NB : b) * DD * DD + (size_t)n0 * DD;

    // fill one k64 chunk into stage s (A: gathered rows; B: weight rows [n][k])
    auto fill = [&](int c, int s) {
        int p = c >> 2, k0 = (c & 3) * 64;
        const __half* Asrc = (p < 2) ? g_xh : g_xl;
        const __half* Bsrc = ((p == 1) ? g_wl : g_wh) + wbase;
        uint32_t base = sb + SM_BUF + (uint32_t)s * STAGE_STRIDE;
#pragma unroll
        for (int i = 0; i < 8; i++) {
            int u = tid + 256 * i;
            int row = (u >> 3) & 127;
            int c16 = u & 7;
            uint32_t dsto = (uint32_t)(row * 8 + (c16 ^ (row & 7))) * 16;
            if (u < 1024)
                cp16(base + dsto, Asrc + (size_t)row_src[row] * DD + k0 + c16 * 8);
            else
                cp16(base + OFF_B + dsto, Bsrc + (size_t)row * DD + k0 + c16 * 8);
        }
        cp_commit();
    };

    float acc[2][8][4];
#pragma unroll
    for (int mi = 0; mi < 2; mi++)
#pragma unroll
        for (int j = 0; j < 8; j++)
#pragma unroll
            for (int q = 0; q < 4; q++) acc[mi][j][q] = 0.f;

    fill(0, 0);
    fill(1, 1);

#pragma unroll 1
    for (int c = 0; c < NCHUNK; c++) {
        int s = c & 1;
        if (c < NCHUNK - 1) cp_wait<1>(); else cp_wait<0>();
        __syncthreads();

        uint32_t ab = sb + SM_BUF + (uint32_t)s * STAGE_STRIDE;
        uint32_t bb = ab + OFF_B;
#pragma unroll
        for (int ks = 0; ks < 4; ks++) {
            uint32_t a[2][4];
            {
                int sub = lid >> 3, r8 = lid & 7;
                int c16 = ks * 2 + (sub >> 1);
#pragma unroll
                for (int mi = 0; mi < 2; mi++) {
                    int row = wm * 32 + mi * 16 + (sub & 1) * 8 + r8;
                    ldsm4(a[mi], ab + (uint32_t)(row * 8 + (c16 ^ (row & 7))) * 16);
                }
            }
#pragma unroll
            for (int nj = 0; nj < 4; nj++) {
                uint32_t bf[4];
                int grp = lid >> 4, half = (lid >> 3) & 1, r8 = lid & 7;
                int nrow = wn * 64 + nj * 16 + grp * 8 + r8;
                int c16 = ks * 2 + half;
                ldsm4(bf, bb + (uint32_t)(nrow * 8 + (c16 ^ (nrow & 7))) * 16);
#pragma unroll
                for (int mi = 0; mi < 2; mi++) {
                    mma16816(acc[mi][nj * 2 + 0], a[mi], bf[0], bf[1]);
                    mma16816(acc[mi][nj * 2 + 1], a[mi], bf[2], bf[3]);
                }
            }
        }
        __syncthreads();                 // all warps done reading stage s
        if (c + 2 < NCHUNK) fill(c + 2, s);
    }

    // ---- epilogue: bias + store/red ------------------------------------------
    const int rbase = wm * 32 + (lid >> 2);
    const int cbase = wn * 64 + 2 * (lid & 3);
#pragma unroll
    for (int mi = 0; mi < 2; mi++) {
#pragma unroll
        for (int half = 0; half < 2; half++) {
            int rl = rbase + mi * 16 + half * 8;
            if ((m0 + rl) >= count) continue;
            int dst = SELF ? (m0 + rl) : row_dst[rl];
            float* orow = out + (size_t)dst * DD + n0;
#pragma unroll
            for (int j = 0; j < 8; j++) {
                int col = cbase + j * 8;
                float v0 = acc[mi][j][half * 2 + 0] + bias[col];
                float v1 = acc[mi][j][half * 2 + 1] + bias[col + 1];
                if (SELF) {
                    float2 v; v.x = v0; v.y = v1;
                    *(float2*)(orow + col) = v;
                } else {
                    red2(orow + col, v0, v1);
                }
            }
        }
    }
}

// ---------------- final ReLU -------------------------------------------------
__global__ void relu_k(float* __restrict__ out) {
    int i = blockIdx.x * blockDim.x + threadIdx.x;
    if (i < NNODE * DD / 4) {
        float4* p = (float4*)out;
        float4 v = p[i];
        v.x = fmaxf(v.x, 0.f); v.y = fmaxf(v.y, 0.f);
        v.z = fmaxf(v.z, 0.f); v.w = fmaxf(v.w, 0.f);
        p[i] = v;
    }
}

// ---------------- launch -----------------------------------------------------
extern "C" void kernel_launch(void* const* d_in, const int* in_sizes, int n_in,
                              void* d_out, int out_size) {
    (void)in_sizes; (void)n_in; (void)out_size;
    const float* x   = (const float*)d_in[0];
    const int*   dep = (const int*)d_in[1];
    const int*   rel = (const int*)d_in[2];
    const int*   gov = (const int*)d_in[3];
    const float* Ws  = (const float*)d_in[4];
    const float* bs  = (const float*)d_in[5];
    const float* Wr  = (const float*)d_in[6];
    const float* br  = (const float*)d_in[7];
    float* out = (float*)d_out;

    cudaFuncSetAttribute(gemm_mma_k<true>,  cudaFuncAttributeMaxDynamicSharedMemorySize, SMEM_TOTAL);
    cudaFuncSetAttribute(gemm_mma_k<false>, cudaFuncAttributeMaxDynamicSharedMemorySize, SMEM_TOTAL);

    // bucketing
    zero_counts_k<<<1, 32>>>();
    hist_k<<<(EE + 255) / 256, 256>>>(rel);
    scan_k<<<1, 32>>>();
    scatter2_k<<<(EE + 255) / 256, 256>>>(dep, rel, gov);

    // fp16 hi/lo prep
    convert_x_k<<<(NNODE * DD + 255) / 256, 256>>>(x);
    convert_w_k<<<((NB + 1) * DD * DD + 255) / 256, 256>>>(Wr, Ws);

    // self transform (plain stores initialize out)
    dim3 gself((NNODE + TM - 1) / TM, 2);
    gemm_mma_k<true><<<gself, 256, SMEM_TOTAL>>>(bs, out);

    // grouped message GEMM (+ atomic scatter-add)
    dim3 gmsg(MAX_TILES, 2);
    gemm_mma_k<false><<<gmsg, 256, SMEM_TOTAL>>>(br, out);

    relu_k<<<(NNODE * DD / 4 + 255) / 256, 256>>>(out);
}

// round 6
// speedup vs baseline: 6.1332x; 1.8107x over previous
#include <cuda_runtime.h>
#include <cuda_fp16.h>
#include <cstdint>

// ---------------- problem constants -----------------------------------------
#define DD    256
#define NNODE 20000
#define RRR   12
#define EE    200000
#define NB    (2*RRR)
#define TM    128
#define MAX_TILES (2*EE/TM + NB + 8)
#define NCHUNK 4             // single fp16 pass: 4 x k64 chunks (K=256)

// ---------------- smem layout -------------------------------------------------
#define SM_ROWSRC 0          // 128 int
#define SM_ROWDST 512        // 128 int
#define SM_BIAS   1024       // 128 float
#define SM_BUF    2048
#define STAGE_STRIDE 32768   // A 16KB + B 16KB
#define OFF_B     16384
#define SMEM_TOTAL (SM_BUF + 2*STAGE_STRIDE)   // 67584 B

// ---------------- device scratch ---------------------------------------------
__device__ int g_count[RRR];
__device__ int g_start[NB + 1];
__device__ int g_cursor[NB];
__device__ int g_src[2 * EE];
__device__ int g_dst[2 * EE];
__device__ int g_tile_info[MAX_TILES];
__device__ int g_total_tiles;

__device__ __half g_xh[NNODE * DD];
__device__ __half g_wh[(NB + 1) * DD * DD];   // [bucket][out=n][in=k]; index NB = W_self

// ---------------- PTX helpers ------------------------------------------------
__device__ __forceinline__ uint32_t smem_u32(const void* p) {
    uint32_t a;
    asm("{ .reg .u64 t; cvta.to.shared.u64 t, %1; cvt.u32.u64 %0, t; }" : "=r"(a) : "l"(p));
    return a;
}
__device__ __forceinline__ void cp16(uint32_t d, const void* s) {
    asm volatile("cp.async.cg.shared.global [%0], [%1], 16;" :: "r"(d), "l"(s) : "memory");
}
__device__ __forceinline__ void cp_commit() {
    asm volatile("cp.async.commit_group;" ::: "memory");
}
template<int N> __device__ __forceinline__ void cp_wait() {
    asm volatile("cp.async.wait_group %0;" :: "n"(N) : "memory");
}
__device__ __forceinline__ void ldsm4(uint32_t* r, uint32_t addr) {
    asm volatile("ldmatrix.sync.aligned.m8n8.x4.shared.b16 {%0,%1,%2,%3}, [%4];"
                 : "=r"(r[0]), "=r"(r[1]), "=r"(r[2]), "=r"(r[3]) : "r"(addr));
}
__device__ __forceinline__ void mma16816(float* c, const uint32_t* a, uint32_t b0, uint32_t b1) {
    asm volatile("mma.sync.aligned.m16n8k16.row.col.f32.f16.f16.f32 "
                 "{%0,%1,%2,%3}, {%4,%5,%6,%7}, {%8,%9}, {%0,%1,%2,%3};"
                 : "+f"(c[0]), "+f"(c[1]), "+f"(c[2]), "+f"(c[3])
                 : "r"(a[0]), "r"(a[1]), "r"(a[2]), "r"(a[3]), "r"(b0), "r"(b1));
}
__device__ __forceinline__ void red2(float* p, float v0, float v1) {
    asm volatile("red.global.add.v2.f32 [%0], {%1,%2};" :: "l"(p), "f"(v0), "f"(v1) : "memory");
}

// ---------------- setup kernels ----------------------------------------------
__global__ void zero_counts_k() {
    if (threadIdx.x < RRR) g_count[threadIdx.x] = 0;
}

__global__ void hist_k(const int* __restrict__ rel) {
    __shared__ int sc[RRR];
    if (threadIdx.x < RRR) sc[threadIdx.x] = 0;
    __syncthreads();
    int i = blockIdx.x * blockDim.x + threadIdx.x;
    if (i < EE) atomicAdd(&sc[rel[i]], 1);
    __syncthreads();
    if (threadIdx.x < RRR && sc[threadIdx.x])
        atomicAdd(&g_count[threadIdx.x], sc[threadIdx.x]);
}

__global__ void scan_k() {
    if (threadIdx.x != 0) return;
    int s = 0, nt = 0;
    for (int b = 0; b < NB; b++) {
        int c = g_count[(b < RRR) ? b : (b - RRR)];
        g_start[b] = s;
        g_cursor[b] = s;
        int tiles = (c + TM - 1) / TM;
        for (int t = 0; t < tiles; t++) g_tile_info[nt++] = (b << 16) | t;
        s += c;
    }
    g_start[NB] = s;
    g_total_tiles = nt;
}

// block-aggregated scatter: smem local offsets + one global atomic per (block,bucket)
__global__ void scatter2_k(const int* __restrict__ dep,
                           const int* __restrict__ rel,
                           const int* __restrict__ gov) {
    __shared__ int sc[NB];
    __shared__ int base[NB];
    int t = threadIdx.x;
    if (t < NB) sc[t] = 0;
    __syncthreads();
    int i = blockIdx.x * blockDim.x + t;
    int r = 0, d = 0, g = 0, l1 = 0, l2 = 0;
    bool v = (i < EE);
    if (v) {
        r = rel[i]; d = dep[i]; g = gov[i];
        l1 = atomicAdd(&sc[r], 1);
        l2 = atomicAdd(&sc[r + RRR], 1);
    }
    __syncthreads();
    if (t < NB) base[t] = sc[t] ? atomicAdd(&g_cursor[t], sc[t]) : 0;
    __syncthreads();
    if (v) {
        int p = base[r] + l1;         g_src[p] = g; g_dst[p] = d;   // forward
        int q = base[r + RRR] + l2;   g_src[q] = d; g_dst[q] = g;   // reverse
    }
}

// ---------------- fp16 conversions -------------------------------------------
__global__ void convert_x_k(const float* __restrict__ x) {
    int i = blockIdx.x * blockDim.x + threadIdx.x;
    if (i < NNODE * DD) g_xh[i] = __float2half_rn(x[i]);
}

__global__ void convert_w_k(const float* __restrict__ Wr, const float* __restrict__ Ws) {
    int i = blockIdx.x * blockDim.x + threadIdx.x;
    if (i >= (NB + 1) * DD * DD) return;
    int b = i >> 16;
    g_wh[i] = __float2half_rn((b < NB) ? Wr[i] : Ws[i & 65535]);
}

// ---------------- grouped GEMM via mma.sync (HMMA) ----------------------------
// CTA: 128(M) x 128(N); grid.y in {0,1} selects N half. 8 warps, warp tile 32x64.
// Single fp16 pass, K=256 as 4 double-buffered k64 chunks, fp32 accumulation.
template<bool SELF>
__global__ __launch_bounds__(256, 2)
void gemm_mma_k(const float* __restrict__ bvec_g, float* __restrict__ out) {
    extern __shared__ char smem[];
    const int tid = threadIdx.x, lid = tid & 31, wid = tid >> 5;
    const int wm = wid >> 1, wn = wid & 1;          // warp grid 4 x 2
    const int n0 = blockIdx.y * 128;

    int b = 0, m0, start = 0, count;
    if (SELF) {
        m0 = blockIdx.x * TM;
        count = NNODE;
    } else {
        if (blockIdx.x >= g_total_tiles) return;
        int info = g_tile_info[blockIdx.x];
        b = info >> 16;
        m0 = (info & 0xFFFF) * TM;
        start = g_start[b];
        count = g_start[b + 1] - start;
    }

    int*   row_src = (int*)smem;
    int*   row_dst = (int*)(smem + SM_ROWDST);
    float* bias    = (float*)(smem + SM_BIAS);
    uint32_t sb = smem_u32(smem);

    if (tid < 128) {
        int m = m0 + tid; if (m >= count) m = count - 1;
        int s, d;
        if (SELF) { s = m; d = m; }
        else      { s = g_src[start + m]; d = g_dst[start + m]; }
        row_src[tid] = s;
        row_dst[tid] = d;
        bias[tid] = SELF ? bvec_g[n0 + tid] : bvec_g[b * DD + n0 + tid];
    }
    __syncthreads();

    const __half* Bsrc = g_wh + (size_t)(SELF ? NB : b) * DD * DD + (size_t)n0 * DD;

    // fill one k64 chunk into stage s (A: gathered rows; B: weight rows [n][k])
    auto fill = [&](int c, int s) {
        int k0 = c * 64;
        uint32_t base = sb + SM_BUF + (uint32_t)s * STAGE_STRIDE;
#pragma unroll
        for (int i = 0; i < 8; i++) {
            int u = tid + 256 * i;
            int row = (u >> 3) & 127;
            int c16 = u & 7;
            uint32_t dsto = (uint32_t)(row * 8 + (c16 ^ (row & 7))) * 16;
            if (u < 1024)
                cp16(base + dsto, g_xh + (size_t)row_src[row] * DD + k0 + c16 * 8);
            else
                cp16(base + OFF_B + dsto, Bsrc + (size_t)row * DD + k0 + c16 * 8);
        }
        cp_commit();
    };

    float acc[2][8][4];
#pragma unroll
    for (int mi = 0; mi < 2; mi++)
#pragma unroll
        for (int j = 0; j < 8; j++)
#pragma unroll
            for (int q = 0; q < 4; q++) acc[mi][j][q] = 0.f;

    fill(0, 0);
    fill(1, 1);

#pragma unroll 1
    for (int c = 0; c < NCHUNK; c++) {
        int s = c & 1;
        if (c < NCHUNK - 1) cp_wait<1>(); else cp_wait<0>();
        __syncthreads();

        uint32_t ab = sb + SM_BUF + (uint32_t)s * STAGE_STRIDE;
        uint32_t bb = ab + OFF_B;
#pragma unroll
        for (int ks = 0; ks < 4; ks++) {
            uint32_t a[2][4];
            {
                int sub = lid >> 3, r8 = lid & 7;
                int c16 = ks * 2 + (sub >> 1);
#pragma unroll
                for (int mi = 0; mi < 2; mi++) {
                    int row = wm * 32 + mi * 16 + (sub & 1) * 8 + r8;
                    ldsm4(a[mi], ab + (uint32_t)(row * 8 + (c16 ^ (row & 7))) * 16);
                }
            }
#pragma unroll
            for (int nj = 0; nj < 4; nj++) {
                uint32_t bf[4];
                int grp = lid >> 4, half = (lid >> 3) & 1, r8 = lid & 7;
                int nrow = wn * 64 + nj * 16 + grp * 8 + r8;
                int c16 = ks * 2 + half;
                ldsm4(bf, bb + (uint32_t)(nrow * 8 + (c16 ^ (nrow & 7))) * 16);
#pragma unroll
                for (int mi = 0; mi < 2; mi++) {
                    mma16816(acc[mi][nj * 2 + 0], a[mi], bf[0], bf[1]);
                    mma16816(acc[mi][nj * 2 + 1], a[mi], bf[2], bf[3]);
                }
            }
        }
        __syncthreads();                 // all warps done reading stage s
        if (c + 2 < NCHUNK) fill(c + 2, s);
    }

    // ---- epilogue: bias + store/red ------------------------------------------
    const int rbase = wm * 32 + (lid >> 2);
    const int cbase = wn * 64 + 2 * (lid & 3);
#pragma unroll
    for (int mi = 0; mi < 2; mi++) {
#pragma unroll
        for (int half = 0; half < 2; half++) {
            int rl = rbase + mi * 16 + half * 8;
            if ((m0 + rl) >= count) continue;
            int dst = SELF ? (m0 + rl) : row_dst[rl];
            float* orow = out + (size_t)dst * DD + n0;
#pragma unroll
            for (int j = 0; j < 8; j++) {
                int col = cbase + j * 8;
                float v0 = acc[mi][j][half * 2 + 0] + bias[col];
                float v1 = acc[mi][j][half * 2 + 1] + bias[col + 1];
                if (SELF) {
                    float2 v; v.x = v0; v.y = v1;
                    *(float2*)(orow + col) = v;
                } else {
                    red2(orow + col, v0, v1);
                }
            }
        }
    }
}

// ---------------- final ReLU -------------------------------------------------
__global__ void relu_k(float* __restrict__ out) {
    int i = blockIdx.x * blockDim.x + threadIdx.x;
    if (i < NNODE * DD / 4) {
        float4* p = (float4*)out;
        float4 v = p[i];
        v.x = fmaxf(v.x, 0.f); v.y = fmaxf(v.y, 0.f);
        v.z = fmaxf(v.z, 0.f); v.w = fmaxf(v.w, 0.f);
        p[i] = v;
    }
}

// ---------------- launch -----------------------------------------------------
extern "C" void kernel_launch(void* const* d_in, const int* in_sizes, int n_in,
                              void* d_out, int out_size) {
    (void)in_sizes; (void)n_in; (void)out_size;
    const float* x   = (const float*)d_in[0];
    const int*   dep = (const int*)d_in[1];
    const int*   rel = (const int*)d_in[2];
    const int*   gov = (const int*)d_in[3];
    const float* Ws  = (const float*)d_in[4];
    const float* bs  = (const float*)d_in[5];
    const float* Wr  = (const float*)d_in[6];
    const float* br  = (const float*)d_in[7];
    float* out = (float*)d_out;

    cudaFuncSetAttribute(gemm_mma_k<true>,  cudaFuncAttributeMaxDynamicSharedMemorySize, SMEM_TOTAL);
    cudaFuncSetAttribute(gemm_mma_k<false>, cudaFuncAttributeMaxDynamicSharedMemorySize, SMEM_TOTAL);

    // bucketing
    zero_counts_k<<<1, 32>>>();
    hist_k<<<(EE + 255) / 256, 256>>>(rel);
    scan_k<<<1, 32>>>();
    scatter2_k<<<(EE + 255) / 256, 256>>>(dep, rel, gov);

    // fp16 prep
    convert_x_k<<<(NNODE * DD + 255) / 256, 256>>>(x);
    convert_w_k<<<((NB + 1) * DD * DD + 255) / 256, 256>>>(Wr, Ws);

    // self transform (plain stores initialize out)
    dim3 gself((NNODE + TM - 1) / TM, 2);
    gemm_mma_k<true><<<gself, 256, SMEM_TOTAL>>>(bs, out);

    // grouped message GEMM (+ atomic scatter-add)
    dim3 gmsg(MAX_TILES, 2);
    gemm_mma_k<false><<<gmsg, 256, SMEM_TOTAL>>>(br, out);

    relu_k<<<(NNODE * DD / 4 + 255) / 256, 256>>>(out);
}